// round 12
// baseline (speedup 1.0000x reference)
#include <cuda_runtime.h>
#include <cstdint>

#define U 128
#define ROW_IN  (4 * U)    // 512 floats per x1 row
#define ROW_OUT (11 * U)   // 1408 floats = 5632 bytes per output row
#define ROWS    4          // batch rows per block
#define NTHREADS 256

__global__ __launch_bounds__(NTHREADS, 6)
void ChannelWiseTensorProduct_85779086836293_kernel(
    const float* __restrict__ x1,
    const float* __restrict__ x2,
    const float* __restrict__ w,
    float* __restrict__ out)
{
    __shared__ __align__(16) float sout[ROWS * ROW_OUT];  // 22528 B, final layout
    __shared__ __align__(16) float sin4[ROWS * ROW_IN];   // 8192 B
    __shared__ float sy[ROWS * 4];
    __shared__ __align__(8) unsigned long long mbar;

    const long long b0 = (long long)blockIdx.x * ROWS;
    const int t = threadIdx.x;

    uint32_t mbar_addr;
    asm("{ .reg .u64 tmp; cvta.to.shared.u64 tmp, %1; cvt.u32.u64 %0, tmp; }"
        : "=r"(mbar_addr) : "l"(static_cast<const void*>(&mbar)));

    // --- Init mbarrier, then issue ONE bulk async read: 8192 B GMEM -> SMEM ---
    if (t == 0) {
        asm volatile("mbarrier.init.shared.b64 [%0], %1;"
                     :: "r"(mbar_addr), "r"(1u) : "memory");
    }
    __syncthreads();

    if (t == 0) {
        asm volatile("mbarrier.arrive.expect_tx.shared.b64 _, [%0], %1;"
                     :: "r"(mbar_addr), "n"(ROWS * ROW_IN * 4) : "memory");
        uint32_t sdst;
        asm("{ .reg .u64 tmp; cvta.to.shared.u64 tmp, %1; cvt.u32.u64 %0, tmp; }"
            : "=r"(sdst) : "l"(static_cast<const void*>(sin4)));
        const float* gsrc = x1 + (size_t)b0 * ROW_IN;
        asm volatile(
            "cp.async.bulk.shared::cta.global.mbarrier::complete_tx::bytes "
            "[%0], [%1], %2, [%3];"
            :: "r"(sdst), "l"(gsrc), "n"(ROWS * ROW_IN * 4), "r"(mbar_addr)
            : "memory");
    }

    // --- Load 4 x2 rows (16 floats) while the bulk read is in flight ---
    if (t < ROWS * 4) sy[t] = __ldcs(&x2[(size_t)b0 * 4 + t]);

    const int u     = t & 127;   // channel
    const int rhalf = t >> 7;    // 0 or 1: which row within each pair

    // Weights: cached broadcast loads (overlap with bulk read)
    const float w0 = w[u];
    const float w1 = w[U + u];
    const float w2 = w[2 * U + u];
    const float w3 = w[3 * U + u];
    const float w4 = w[4 * U + u];

    // --- Wait for the input tile ---
    {
        uint32_t done;
        asm volatile(
            "{\n\t"
            ".reg .pred p;\n\t"
            "mbarrier.try_wait.parity.acquire.cta.shared::cta.b64 p, [%1], %2;\n\t"
            "selp.b32 %0, 1, 0, p;\n\t"
            "}"
            : "=r"(done) : "r"(mbar_addr), "r"(0u) : "memory");
        if (!done) {
            asm volatile(
                "{\n\t"
                ".reg .pred P1;\n\t"
                "WAIT_LOOP_%=:\n\t"
                "mbarrier.try_wait.parity.acquire.cta.shared::cta.b64 P1, [%0], %1, 0x989680;\n\t"
                "@P1 bra.uni WAIT_DONE_%=;\n\t"
                "bra.uni WAIT_LOOP_%=;\n\t"
                "WAIT_DONE_%=:\n\t"
                "}"
                :: "r"(mbar_addr), "r"(0u) : "memory");
        }
    }
    __syncthreads();   // sy visibility + all threads past input wait

    const float INV_SQRT3 = 0.57735026918962576451f;
    const float INV_SQRT2 = 0.70710678118654752440f;

    #pragma unroll
    for (int r = 0; r < 2; r++) {
        const int row = 2 * r + rhalf;
        const float* sr = sin4 + row * ROW_IN;
        float* so = sout + row * ROW_OUT;

        const float y0  = sy[row * 4 + 0];
        const float y10 = sy[row * 4 + 1];
        const float y11 = sy[row * 4 + 2];
        const float y12 = sy[row * 4 + 3];

        const float s0 = sr[u];
        const float a0 = sr[U + 3 * u + 0];
        const float a1 = sr[U + 3 * u + 1];
        const float a2 = sr[U + 3 * u + 2];

        // o0
        so[u] = w0 * s0 * y0;

        // o1 at [U .. 4U)
        const float ws0 = w1 * s0;
        so[U + 3 * u + 0] = ws0 * y10;
        so[U + 3 * u + 1] = ws0 * y11;
        so[U + 3 * u + 2] = ws0 * y12;

        // o2 at [4U .. 7U)
        const float wy = w2 * y0;
        so[4 * U + 3 * u + 0] = wy * a0;
        so[4 * U + 3 * u + 1] = wy * a1;
        so[4 * U + 3 * u + 2] = wy * a2;

        // o3 at [7U .. 8U)
        so[7 * U + u] = w3 * (a0 * y10 + a1 * y11 + a2 * y12) * INV_SQRT3;

        // o4 at [8U .. 11U)
        const float c0 = a1 * y12 - a2 * y11;
        const float c1 = a2 * y10 - a0 * y12;
        const float c2 = a0 * y11 - a1 * y10;
        const float w4s = w4 * INV_SQRT2;
        so[8 * U + 3 * u + 0] = w4s * c0;
        so[8 * U + 3 * u + 1] = w4s * c1;
        so[8 * U + 3 * u + 2] = w4s * c2;
    }

    __syncthreads();

    // --- One bulk async store: 22528 contiguous bytes SMEM -> GMEM ---
    if (t == 0) {
        asm volatile("fence.proxy.async.shared::cta;" ::: "memory");

        uint32_t saddr;
        asm("{ .reg .u64 tmp; cvta.to.shared.u64 tmp, %1; cvt.u32.u64 %0, tmp; }"
            : "=r"(saddr) : "l"(static_cast<const void*>(sout)));

        const float* gdst = out + (size_t)b0 * ROW_OUT;
        asm volatile(
            "cp.async.bulk.global.shared::cta.bulk_group [%0], [%1], %2;"
            :: "l"(gdst), "r"(saddr), "n"(ROWS * ROW_OUT * 4)
            : "memory");
        asm volatile("cp.async.bulk.commit_group;" ::: "memory");
        asm volatile("cp.async.bulk.wait_group 0;" ::: "memory");
    }
}

extern "C" void kernel_launch(void* const* d_in, const int* in_sizes, int n_in,
                              void* d_out, int out_size) {
    const float* x1 = (const float*)d_in[0];
    const float* x2 = (const float*)d_in[1];
    const float* w  = (const float*)d_in[2];
    float* out = (float*)d_out;

    const int B = in_sizes[0] / ROW_IN;  // 65536
    ChannelWiseTensorProduct_85779086836293_kernel<<<B / ROWS, NTHREADS>>>(x1, x2, w, out);
}

// round 13
// speedup vs baseline: 1.0029x; 1.0029x over previous
#include <cuda_runtime.h>
#include <cstdint>

#define U 128
#define ROW_IN  (4 * U)    // 512 floats per x1 row
#define ROW_OUT (11 * U)   // 1408 floats = 5632 bytes per output row
#define ROWS    8          // batch rows per block
#define NTHREADS 512

__global__ __launch_bounds__(NTHREADS, 3)
void ChannelWiseTensorProduct_85779086836293_kernel(
    const float* __restrict__ x1,
    const float* __restrict__ x2,
    const float* __restrict__ w,
    float* __restrict__ out)
{
    __shared__ __align__(16) float sout[ROWS * ROW_OUT];  // 45056 B, final layout
    __shared__ __align__(16) float sin8[ROWS * ROW_IN];   // 16384 B
    __shared__ float sy[ROWS * 4];

    const long long b0 = (long long)blockIdx.x * ROWS;
    const int t = threadIdx.x;

    // --- Load 8 input rows (4096 floats = 1024 float4), fully coalesced, 2/thread ---
    const float4* x1v = reinterpret_cast<const float4*>(x1 + (size_t)b0 * ROW_IN);
    float4* sv = reinterpret_cast<float4*>(sin8);
    sv[t]       = __ldcs(&x1v[t]);
    sv[t + 512] = __ldcs(&x1v[t + 512]);

    // --- Load 8 x2 rows (32 floats) ---
    if (t < ROWS * 4) sy[t] = __ldcs(&x2[(size_t)b0 * 4 + t]);

    __syncthreads();

    const int u    = t & 127;   // channel
    const int rq   = t >> 7;    // 0..3: row-quarter

    // Weights: cached broadcast loads
    const float w0 = w[u];
    const float w1 = w[U + u];
    const float w2 = w[2 * U + u];
    const float w3 = w[3 * U + u];
    const float w4 = w[4 * U + u];

    const float INV_SQRT3 = 0.57735026918962576451f;
    const float INV_SQRT2 = 0.70710678118654752440f;

    #pragma unroll
    for (int r = 0; r < 2; r++) {
        const int row = 4 * r + rq;                 // rows 0..7 covered
        const float* sr = sin8 + row * ROW_IN;
        float* so = sout + row * ROW_OUT;

        const float y0  = sy[row * 4 + 0];
        const float y10 = sy[row * 4 + 1];
        const float y11 = sy[row * 4 + 2];
        const float y12 = sy[row * 4 + 3];

        const float s0 = sr[u];
        const float a0 = sr[U + 3 * u + 0];
        const float a1 = sr[U + 3 * u + 1];
        const float a2 = sr[U + 3 * u + 2];

        // o0
        so[u] = w0 * s0 * y0;

        // o1 at [U .. 4U)
        const float ws0 = w1 * s0;
        so[U + 3 * u + 0] = ws0 * y10;
        so[U + 3 * u + 1] = ws0 * y11;
        so[U + 3 * u + 2] = ws0 * y12;

        // o2 at [4U .. 7U)
        const float wy = w2 * y0;
        so[4 * U + 3 * u + 0] = wy * a0;
        so[4 * U + 3 * u + 1] = wy * a1;
        so[4 * U + 3 * u + 2] = wy * a2;

        // o3 at [7U .. 8U)
        so[7 * U + u] = w3 * (a0 * y10 + a1 * y11 + a2 * y12) * INV_SQRT3;

        // o4 at [8U .. 11U)
        const float c0 = a1 * y12 - a2 * y11;
        const float c1 = a2 * y10 - a0 * y12;
        const float c2 = a0 * y11 - a1 * y10;
        const float w4s = w4 * INV_SQRT2;
        so[8 * U + 3 * u + 0] = w4s * c0;
        so[8 * U + 3 * u + 1] = w4s * c1;
        so[8 * U + 3 * u + 2] = w4s * c2;
    }

    __syncthreads();

    // --- One bulk async store: 45056 contiguous bytes SMEM -> GMEM ---
    if (t == 0) {
        asm volatile("fence.proxy.async.shared::cta;" ::: "memory");

        uint32_t saddr;
        asm("{ .reg .u64 tmp; cvta.to.shared.u64 tmp, %1; cvt.u32.u64 %0, tmp; }"
            : "=r"(saddr) : "l"(static_cast<const void*>(sout)));

        const float* gdst = out + (size_t)b0 * ROW_OUT;
        asm volatile(
            "cp.async.bulk.global.shared::cta.bulk_group [%0], [%1], %2;"
            :: "l"(gdst), "r"(saddr), "n"(ROWS * ROW_OUT * 4)
            : "memory");
        asm volatile("cp.async.bulk.commit_group;" ::: "memory");
        asm volatile("cp.async.bulk.wait_group 0;" ::: "memory");
    }
}

extern "C" void kernel_launch(void* const* d_in, const int* in_sizes, int n_in,
                              void* d_out, int out_size) {
    const float* x1 = (const float*)d_in[0];
    const float* x2 = (const float*)d_in[1];
    const float* w  = (const float*)d_in[2];
    float* out = (float*)d_out;

    const int B = in_sizes[0] / ROW_IN;  // 65536
    ChannelWiseTensorProduct_85779086836293_kernel<<<B / ROWS, NTHREADS>>>(x1, x2, w, out);
}